// round 3
// baseline (speedup 1.0000x reference)
#include <cuda_runtime.h>

#define C 128
#define TILE 64
#define THREADS 256
#define RPW 8          // rows per warp (8 warps * 8 rows = 64)
#define EPSF 1e-8f

// Precomputed score matrices M = (Wq @ Wk^T) / sqrt(C), per branch.
__device__ float g_Mm[C * C];
__device__ float g_Md[C * C];

// ---------------------------------------------------------------------------
// K0: M[i][i'] = sum_j Wq[i][j] * Wk[i'][j] / sqrt(C)
// grid (128, 2), block 128. Tiny (2 x 2M MACs), cost is noise.
// ---------------------------------------------------------------------------
__global__ void precompute_M_kernel(const float* __restrict__ Wq_m,
                                    const float* __restrict__ Wk_m,
                                    const float* __restrict__ Wq_d,
                                    const float* __restrict__ Wk_d) {
    const float* Wq = blockIdx.y ? Wq_d : Wq_m;
    const float* Wk = blockIdx.y ? Wk_d : Wk_m;
    float* M = blockIdx.y ? g_Md : g_Mm;
    int i = blockIdx.x, t = threadIdx.x;
    __shared__ float qrow[C];
    qrow[t] = Wq[i * C + t];
    __syncthreads();
    const float* wkr = Wk + t * C;
    float acc = 0.f;
#pragma unroll 8
    for (int j = 0; j < C; j++) acc += qrow[j] * wkr[j];
    M[i * C + t] = acc * 0.08838834764831845f;  // 1/sqrt(128)
}

// ---------------------------------------------------------------------------
// K1: fully fused per-row pipeline.
// SMEM: em/ed/x0/x1 tiles (64x128 f32 each) + one 128x128 weight slot + W2.
// ---------------------------------------------------------------------------
__global__ void __launch_bounds__(THREADS, 1)
fused_kernel(const float* __restrict__ em, const float* __restrict__ ed,
             const float* __restrict__ W_gcn, const float* __restrict__ Wv_m,
             const float* __restrict__ Wv_d, const float* __restrict__ W1,
             const float* __restrict__ W2, float* __restrict__ out) {
    extern __shared__ float sm[];
    float* sEM = sm;                 // TILE*C
    float* sED = sEM + TILE * C;     // TILE*C
    float* sX0 = sED + TILE * C;     // TILE*C
    float* sX1 = sX0 + TILE * C;     // TILE*C
    float* sW  = sX1 + TILE * C;     // C*C
    float* sW2 = sW + C * C;         // C

    const int tid = threadIdx.x;
    const int lane = tid & 31;
    const int w = tid >> 5;
    const int r0 = w * RPW;
    const long base = (long)blockIdx.x * TILE;

    // ---- load em / ed tile (vectorized, coalesced) ----
    {
        const float4* ge = (const float4*)(em + base * C);
        const float4* gd = (const float4*)(ed + base * C);
        float4* se = (float4*)sEM;
        float4* sd = (float4*)sED;
        for (int i = tid; i < TILE * C / 4; i += THREADS) {
            se[i] = ge[i];
            sd[i] = gd[i];
        }
        if (tid < C) sW2[tid] = W2[tid];
    }
    __syncthreads();

    // ---- per-row adjacency scalars a, b ----
    float aS[RPW], bS[RPW];
#pragma unroll
    for (int rr = 0; rr < RPW; rr++) {
        const float* pe = sEM + (r0 + rr) * C;
        const float* pd = sED + (r0 + rr) * C;
        float sa = 0.f, q0 = 0.f, q1 = 0.f, dp = 0.f;
#pragma unroll
        for (int q = 0; q < 4; q++) {
            int k = lane + 32 * q;
            float e = pe[k], d = pd[k];
            sa += fabsf(e - d);
            q0 += e * e;
            q1 += d * d;
            dp += e * d;
        }
#pragma unroll
        for (int o = 16; o; o >>= 1) {
            sa += __shfl_xor_sync(~0u, sa, o);
            q0 += __shfl_xor_sync(~0u, q0, o);
            q1 += __shfl_xor_sync(~0u, q1, o);
            dp += __shfl_xor_sync(~0u, dp, o);
        }
        float m = sa;  // lrelu(m) == m since m >= 0
        float cosv = dp / (sqrtf(q0 + EPSF) * sqrtf(q1 + EPSF));
        float cp = cosv > 0.f ? cosv : 0.01f * cosv;
        float a1 = 1.f / (1.f + cp), b1 = cp / (1.f + cp);
        float a3 = 1.f / (1.f + m),  b3 = m  / (1.f + m);
        aS[rr] = fminf(a1, a3);
        bS[rr] = fminf(b1, b3);
    }

    // weight stager: sync, copy 64KB into the shared slot, sync
    auto load_w = [&](const float* g) {
        __syncthreads();
        float4* d4 = (float4*)sW;
        const float4* s4 = (const float4*)g;
        for (int i = tid; i < C * C / 4; i += THREADS) d4[i] = s4[i];
        __syncthreads();
    };

    // ---- GCN: g0 = em@W, g1 = ed@W; x1_* = relu(pL @ g) + x0 ----
    load_w(W_gcn);
    {
        float A0[RPW][4] = {}, A1[RPW][4] = {};
        const float4* w4 = (const float4*)sW;
#pragma unroll 2
        for (int k = 0; k < C; k++) {
            float4 wv = w4[k * 32 + lane];
#pragma unroll
            for (int rr = 0; rr < RPW; rr++) {
                float e = sEM[(r0 + rr) * C + k];
                float d = sED[(r0 + rr) * C + k];
                A0[rr][0] += e * wv.x; A0[rr][1] += e * wv.y;
                A0[rr][2] += e * wv.z; A0[rr][3] += e * wv.w;
                A1[rr][0] += d * wv.x; A1[rr][1] += d * wv.y;
                A1[rr][2] += d * wv.z; A1[rr][3] += d * wv.w;
            }
        }
        int j = lane * 4;
#pragma unroll
        for (int rr = 0; rr < RPW; rr++) {
            float4 e4 = *(const float4*)(sEM + (r0 + rr) * C + j);
            float4 d4 = *(const float4*)(sED + (r0 + rr) * C + j);
            float a = aS[rr], b = bS[rr];
            float4 x0, x1;
            x0.x = fmaxf(a * A0[rr][0] + b * A1[rr][0], 0.f) + e4.x;
            x0.y = fmaxf(a * A0[rr][1] + b * A1[rr][1], 0.f) + e4.y;
            x0.z = fmaxf(a * A0[rr][2] + b * A1[rr][2], 0.f) + e4.z;
            x0.w = fmaxf(a * A0[rr][3] + b * A1[rr][3], 0.f) + e4.w;
            x1.x = fmaxf(b * A0[rr][0] + a * A1[rr][0], 0.f) + d4.x;
            x1.y = fmaxf(b * A0[rr][1] + a * A1[rr][1], 0.f) + d4.y;
            x1.z = fmaxf(b * A0[rr][2] + a * A1[rr][2], 0.f) + d4.z;
            x1.w = fmaxf(b * A0[rr][3] + a * A1[rr][3], 0.f) + d4.w;
            *(float4*)(sX0 + (r0 + rr) * C + j) = x0;
            *(float4*)(sX1 + (r0 + rr) * C + j) = x1;
        }
        __syncwarp();
    }

    // ---- attention branch (shared code for m / d) ----
    // t = x_last @ M; s0 = t.x_first; s1 = t.x_last; u = w0*x_first + w1*x_last (in place)
    auto attn_scores_u = [&](const float* sFirst, float* sLast) {
        float T[RPW][4] = {};
        const float4* w4 = (const float4*)sW;
#pragma unroll 2
        for (int k = 0; k < C; k++) {
            float4 wv = w4[k * 32 + lane];
#pragma unroll
            for (int rr = 0; rr < RPW; rr++) {
                float x = sLast[(r0 + rr) * C + k];
                T[rr][0] += x * wv.x; T[rr][1] += x * wv.y;
                T[rr][2] += x * wv.z; T[rr][3] += x * wv.w;
            }
        }
        int j = lane * 4;
#pragma unroll
        for (int rr = 0; rr < RPW; rr++) {
            float4 f4 = *(const float4*)(sFirst + (r0 + rr) * C + j);
            float4 l4 = *(const float4*)(sLast + (r0 + rr) * C + j);
            float s0 = T[rr][0] * f4.x + T[rr][1] * f4.y + T[rr][2] * f4.z + T[rr][3] * f4.w;
            float s1 = T[rr][0] * l4.x + T[rr][1] * l4.y + T[rr][2] * l4.z + T[rr][3] * l4.w;
#pragma unroll
            for (int o = 16; o; o >>= 1) {
                s0 += __shfl_xor_sync(~0u, s0, o);
                s1 += __shfl_xor_sync(~0u, s1, o);
            }
            float mx = fmaxf(s0, s1);
            float e0 = expf(s0 - mx), e1 = expf(s1 - mx);
            float inv = 1.f / (e0 + e1);
            float w0 = e0 * inv, w1 = e1 * inv;
            float4 u;
            u.x = w0 * f4.x + w1 * l4.x;
            u.y = w0 * f4.y + w1 * l4.y;
            u.z = w0 * f4.z + w1 * l4.z;
            u.w = w0 * f4.w + w1 * l4.w;
            *(float4*)(sLast + (r0 + rr) * C + j) = u;
        }
        __syncwarp();
    };

    // u @ Wv -> overwrite sBuf rows with LA output
    auto matvec_inplace = [&](float* sBuf) {
        float Acc[RPW][4] = {};
        const float4* w4 = (const float4*)sW;
#pragma unroll 2
        for (int k = 0; k < C; k++) {
            float4 wv = w4[k * 32 + lane];
#pragma unroll
            for (int rr = 0; rr < RPW; rr++) {
                float x = sBuf[(r0 + rr) * C + k];
                Acc[rr][0] += x * wv.x; Acc[rr][1] += x * wv.y;
                Acc[rr][2] += x * wv.z; Acc[rr][3] += x * wv.w;
            }
        }
        __syncwarp();
        int j = lane * 4;
#pragma unroll
        for (int rr = 0; rr < RPW; rr++) {
            *(float4*)(sBuf + (r0 + rr) * C + j) =
                make_float4(Acc[rr][0], Acc[rr][1], Acc[rr][2], Acc[rr][3]);
        }
        __syncwarp();
    };

    // m-branch: layers [em, x1_0], query = x1_0
    load_w(g_Mm);
    attn_scores_u(sEM, sX0);
    load_w(Wv_m);
    matvec_inplace(sX0);   // sX0 now holds mLA

    // d-branch: layers [ed, x1_1], query = x1_1
    load_w(g_Md);
    attn_scores_u(sED, sX1);
    load_w(Wv_d);
    matvec_inplace(sX1);   // sX1 now holds dLA

    // ---- head: h = relu((mLA*dLA) @ W1); pre = h . W2; sigmoid ----
    load_w(W1);
    {
        float H[RPW][4] = {};
        const float4* w4 = (const float4*)sW;
#pragma unroll 2
        for (int k = 0; k < C; k++) {
            float4 wv = w4[k * 32 + lane];
#pragma unroll
            for (int rr = 0; rr < RPW; rr++) {
                float ne = sX0[(r0 + rr) * C + k] * sX1[(r0 + rr) * C + k];
                H[rr][0] += ne * wv.x; H[rr][1] += ne * wv.y;
                H[rr][2] += ne * wv.z; H[rr][3] += ne * wv.w;
            }
        }
        int j = lane * 4;
#pragma unroll
        for (int rr = 0; rr < RPW; rr++) {
            float p = fmaxf(H[rr][0], 0.f) * sW2[j]
                    + fmaxf(H[rr][1], 0.f) * sW2[j + 1]
                    + fmaxf(H[rr][2], 0.f) * sW2[j + 2]
                    + fmaxf(H[rr][3], 0.f) * sW2[j + 3];
#pragma unroll
            for (int o = 16; o; o >>= 1) p += __shfl_xor_sync(~0u, p, o);
            if (lane == 0)
                out[base + r0 + rr] = 1.f / (1.f + expf(-p));
        }
    }
}

// ---------------------------------------------------------------------------
extern "C" void kernel_launch(void* const* d_in, const int* in_sizes, int n_in,
                              void* d_out, int out_size) {
    const float* em    = (const float*)d_in[0];
    const float* ed    = (const float*)d_in[1];
    const float* W_gcn = (const float*)d_in[2];
    const float* Wq_m  = (const float*)d_in[3];
    const float* Wk_m  = (const float*)d_in[4];
    const float* Wv_m  = (const float*)d_in[5];
    const float* Wq_d  = (const float*)d_in[6];
    const float* Wk_d  = (const float*)d_in[7];
    const float* Wv_d  = (const float*)d_in[8];
    const float* W1    = (const float*)d_in[9];
    const float* W2    = (const float*)d_in[10];
    float* out = (float*)d_out;

    const int B = in_sizes[0] / C;           // 262144
    const int smem_bytes = (4 * TILE * C + C * C + C) * (int)sizeof(float);  // 197120

    precompute_M_kernel<<<dim3(C, 2), C>>>(Wq_m, Wk_m, Wq_d, Wk_d);

    cudaFuncSetAttribute(fused_kernel,
                         cudaFuncAttributeMaxDynamicSharedMemorySize, smem_bytes);
    fused_kernel<<<B / TILE, THREADS, smem_bytes>>>(em, ed, W_gcn, Wv_m, Wv_d,
                                                    W1, W2, out);
}

// round 4
// speedup vs baseline: 1.4382x; 1.4382x over previous
#include <cuda_runtime.h>
#include <cuda_bf16.h>
#include <cstdint>

#define C   128
#define LD  132          // padded smem tile stride (floats): 16B-aligned rows, conflict-free B gathers
#define TILE 64
#define THREADS 256
#define RPW 8
#define EPSF 1e-8f

// Precomputed score matrices M = (Wq @ Wk^T)/sqrt(C)
__device__ float g_Mm[C * C];
__device__ float g_Md[C * C];

__global__ void precompute_M_kernel(const float* __restrict__ Wq_m, const float* __restrict__ Wk_m,
                                    const float* __restrict__ Wq_d, const float* __restrict__ Wk_d) {
    const float* Wq = blockIdx.y ? Wq_d : Wq_m;
    const float* Wk = blockIdx.y ? Wk_d : Wk_m;
    float* M = blockIdx.y ? g_Md : g_Mm;
    int i = blockIdx.x, t = threadIdx.x;
    __shared__ float qrow[C];
    qrow[t] = Wq[i * C + t];
    __syncthreads();
    const float* wkr = Wk + t * C;
    float acc = 0.f;
#pragma unroll 8
    for (int j = 0; j < C; j++) acc += qrow[j] * wkr[j];
    M[i * C + t] = acc * 0.08838834764831845f;
}

// split fp32 pair -> packed bf16x2 hi (truncated) + lo (rounded remainder)
__device__ __forceinline__ void split_pack(float x0, float x1, uint32_t& h, uint32_t& l) {
    uint32_t u0 = __float_as_uint(x0), u1 = __float_as_uint(x1);
    h = __byte_perm(u0, u1, 0x7632);  // {top16(x0), top16(x1)}
    float l0 = x0 - __uint_as_float(u0 & 0xFFFF0000u);
    float l1 = x1 - __uint_as_float(u1 & 0xFFFF0000u);
    __nv_bfloat162 t = __floats2bfloat162_rn(l0, l1);
    l = *(uint32_t*)&t;
}

__device__ __forceinline__ void mma16816(float* d, const uint32_t* a, uint32_t b0, uint32_t b1) {
    asm volatile(
        "mma.sync.aligned.m16n8k16.row.col.f32.bf16.bf16.f32 "
        "{%0,%1,%2,%3}, {%4,%5,%6,%7}, {%8,%9}, {%0,%1,%2,%3};"
        : "+f"(d[0]), "+f"(d[1]), "+f"(d[2]), "+f"(d[3])
        : "r"(a[0]), "r"(a[1]), "r"(a[2]), "r"(a[3]), "r"(b0), "r"(b1));
}

// block-wide GEMM: D[64,128] = A[64,128] @ B[128,128], all fp32 smem (stride LD).
// bf16-split, 3 passes. Warp w: rows (w&3)*16..+15, cols (w>>2)*64..+63.
// Safe for D aliasing B (full compute into regs, then sync, then store).
__device__ void wgemm(const float* sA, const float* sB, float* sD, int tid) {
    const int lane = tid & 31;
    const int rb = (tid >> 5 & 3) * 16, ch = (tid >> 7) * 64;
    const int g = lane >> 2, t = lane & 3;
    float acc[8][4];
#pragma unroll
    for (int nt = 0; nt < 8; nt++) acc[nt][0] = acc[nt][1] = acc[nt][2] = acc[nt][3] = 0.f;

#pragma unroll 1
    for (int k0 = 0; k0 < C; k0 += 16) {
        const float* Ar = sA + (rb + g) * LD + k0 + 2 * t;
        float2 p0 = *(const float2*)(Ar);
        float2 p1 = *(const float2*)(Ar + 8 * LD);
        float2 p2 = *(const float2*)(Ar + 8);
        float2 p3 = *(const float2*)(Ar + 8 * LD + 8);
        uint32_t ah[4], al[4];
        split_pack(p0.x, p0.y, ah[0], al[0]);
        split_pack(p1.x, p1.y, ah[1], al[1]);
        split_pack(p2.x, p2.y, ah[2], al[2]);
        split_pack(p3.x, p3.y, ah[3], al[3]);
        const float* Bc = sB + (k0 + 2 * t) * LD + ch + g;
#pragma unroll
        for (int nt = 0; nt < 8; nt++) {
            const float* bp = Bc + nt * 8;
            float b0 = bp[0], b1 = bp[LD], b2 = bp[8 * LD], b3 = bp[9 * LD];
            uint32_t bh0, bl0, bh1, bl1;
            split_pack(b0, b1, bh0, bl0);
            split_pack(b2, b3, bh1, bl1);
            mma16816(acc[nt], ah, bh0, bh1);
            mma16816(acc[nt], al, bh0, bh1);
            mma16816(acc[nt], ah, bl0, bl1);
        }
    }
    __syncthreads();
#pragma unroll
    for (int nt = 0; nt < 8; nt++) {
        float* Dp = sD + (rb + g) * LD + ch + nt * 8 + 2 * t;
        Dp[0] = acc[nt][0];
        Dp[1] = acc[nt][1];
        Dp[8 * LD] = acc[nt][2];
        Dp[8 * LD + 1] = acc[nt][3];
    }
    __syncthreads();
}

__global__ void __launch_bounds__(THREADS, 1)
fused_kernel(const float* __restrict__ em, const float* __restrict__ ed,
             const float* __restrict__ W_gcn, const float* __restrict__ Wv_m,
             const float* __restrict__ Wv_d, const float* __restrict__ W1,
             const float* __restrict__ W2, float* __restrict__ out) {
    extern __shared__ float sm[];
    float* sEM = sm;                   // 64 x LD
    float* sED = sEM + TILE * LD;
    float* sX0 = sED + TILE * LD;
    float* sX1 = sX0 + TILE * LD;
    float* sW  = sX1 + TILE * LD;      // 128 x LD (weight slot; also T/H scratch)
    float* sW2 = sW + C * LD;

    const int tid = threadIdx.x;
    const int lane = tid & 31;
    const int r0 = (tid >> 5) * RPW;
    const long base = (long)blockIdx.x * TILE;

    // load em/ed tiles (row-major global -> stride-LD smem)
    {
        const float4* ge = (const float4*)(em + base * C);
        const float4* gd = (const float4*)(ed + base * C);
        for (int i = tid; i < TILE * 32; i += THREADS) {
            int r = i >> 5, c4 = i & 31;
            ((float4*)(sEM + r * LD))[c4] = ge[i];
            ((float4*)(sED + r * LD))[c4] = gd[i];
        }
        if (tid < C) sW2[tid] = W2[tid];
    }
    __syncthreads();

    // per-row adjacency scalars
    float aS[RPW], bS[RPW];
#pragma unroll
    for (int rr = 0; rr < RPW; rr++) {
        const float* pe = sEM + (r0 + rr) * LD;
        const float* pd = sED + (r0 + rr) * LD;
        float sa = 0.f, q0 = 0.f, q1 = 0.f, dp = 0.f;
#pragma unroll
        for (int q = 0; q < 4; q++) {
            int k = lane + 32 * q;
            float e = pe[k], d = pd[k];
            sa += fabsf(e - d); q0 += e * e; q1 += d * d; dp += e * d;
        }
#pragma unroll
        for (int o = 16; o; o >>= 1) {
            sa += __shfl_xor_sync(~0u, sa, o);
            q0 += __shfl_xor_sync(~0u, q0, o);
            q1 += __shfl_xor_sync(~0u, q1, o);
            dp += __shfl_xor_sync(~0u, dp, o);
        }
        float m = sa;
        float cosv = dp / (sqrtf(q0 + EPSF) * sqrtf(q1 + EPSF));
        float cp = cosv > 0.f ? cosv : 0.01f * cosv;
        aS[rr] = fminf(1.f / (1.f + cp), 1.f / (1.f + m));
        bS[rr] = fminf(cp / (1.f + cp), m / (1.f + m));
    }

    auto load_w = [&](const float* g) {
        __syncthreads();
        const float4* g4 = (const float4*)g;
        for (int i = tid; i < C * 32; i += THREADS) {
            int r = i >> 5, c4 = i & 31;
            ((float4*)(sW + r * LD))[c4] = g4[i];
        }
        __syncthreads();
    };

    // ---- GCN ----
    load_w(W_gcn);
    wgemm(sEM, sW, sX0, tid);   // g0
    wgemm(sED, sW, sX1, tid);   // g1
#pragma unroll
    for (int rr = 0; rr < RPW; rr++) {
        int r = r0 + rr;
        float a = aS[rr], b = bS[rr];
#pragma unroll
        for (int q = 0; q < 4; q++) {
            int k = lane + 32 * q;
            float g0 = sX0[r * LD + k], g1 = sX1[r * LD + k];
            sX0[r * LD + k] = fmaxf(a * g0 + b * g1, 0.f) + sEM[r * LD + k];
            sX1[r * LD + k] = fmaxf(b * g0 + a * g1, 0.f) + sED[r * LD + k];
        }
    }

    // attention epilogue: T in sW rows 0..63; u overwrites sX
    auto attn_epi = [&](const float* sF, float* sX) {
#pragma unroll
        for (int rr = 0; rr < RPW; rr++) {
            int r = r0 + rr;
            float s0 = 0.f, s1 = 0.f;
#pragma unroll
            for (int q = 0; q < 4; q++) {
                int k = lane + 32 * q;
                float tv = sW[r * LD + k];
                s0 += tv * sF[r * LD + k];
                s1 += tv * sX[r * LD + k];
            }
#pragma unroll
            for (int o = 16; o; o >>= 1) {
                s0 += __shfl_xor_sync(~0u, s0, o);
                s1 += __shfl_xor_sync(~0u, s1, o);
            }
            float mx = fmaxf(s0, s1);
            float e0 = expf(s0 - mx), e1 = expf(s1 - mx);
            float inv = 1.f / (e0 + e1);
            float w0 = e0 * inv, w1 = e1 * inv;
#pragma unroll
            for (int q = 0; q < 4; q++) {
                int k = lane + 32 * q;
                sX[r * LD + k] = w0 * sF[r * LD + k] + w1 * sX[r * LD + k];
            }
        }
        __syncthreads();
    };

    // ---- m branch ----
    load_w(g_Mm);
    wgemm(sX0, sW, sW, tid);    // T_m -> sW scratch
    attn_epi(sEM, sX0);         // u_m -> sX0
    load_w(Wv_m);
    wgemm(sX0, sW, sEM, tid);   // mLA -> sEM

    // ---- d branch ----
    load_w(g_Md);
    wgemm(sX1, sW, sW, tid);    // T_d
    attn_epi(sED, sX1);         // u_d -> sX1
    load_w(Wv_d);
    wgemm(sX1, sW, sED, tid);   // dLA -> sED

    // ---- head ----
#pragma unroll
    for (int rr = 0; rr < RPW; rr++) {
        int r = r0 + rr;
#pragma unroll
        for (int q = 0; q < 4; q++) {
            int k = lane + 32 * q;
            sX0[r * LD + k] = sEM[r * LD + k] * sED[r * LD + k];  // ne
        }
    }
    load_w(W1);
    wgemm(sX0, sW, sW, tid);    // H -> sW scratch
#pragma unroll
    for (int rr = 0; rr < RPW; rr++) {
        int r = r0 + rr;
        float p = 0.f;
#pragma unroll
        for (int q = 0; q < 4; q++) {
            int k = lane + 32 * q;
            p += fmaxf(sW[r * LD + k], 0.f) * sW2[k];
        }
#pragma unroll
        for (int o = 16; o; o >>= 1) p += __shfl_xor_sync(~0u, p, o);
        if (lane == 0) out[base + r] = 1.f / (1.f + expf(-p));
    }
}

extern "C" void kernel_launch(void* const* d_in, const int* in_sizes, int n_in,
                              void* d_out, int out_size) {
    const float* em    = (const float*)d_in[0];
    const float* ed    = (const float*)d_in[1];
    const float* W_gcn = (const float*)d_in[2];
    const float* Wq_m  = (const float*)d_in[3];
    const float* Wk_m  = (const float*)d_in[4];
    const float* Wv_m  = (const float*)d_in[5];
    const float* Wq_d  = (const float*)d_in[6];
    const float* Wk_d  = (const float*)d_in[7];
    const float* Wv_d  = (const float*)d_in[8];
    const float* W1    = (const float*)d_in[9];
    const float* W2    = (const float*)d_in[10];
    float* out = (float*)d_out;

    const int B = in_sizes[0] / C;
    const int smem_bytes = (4 * TILE * LD + C * LD + C) * (int)sizeof(float);  // ~203 KB

    precompute_M_kernel<<<dim3(C, 2), C>>>(Wq_m, Wk_m, Wq_d, Wk_d);

    cudaFuncSetAttribute(fused_kernel,
                         cudaFuncAttributeMaxDynamicSharedMemorySize, smem_bytes);
    fused_kernel<<<B / TILE, THREADS, smem_bytes>>>(em, ed, W_gcn, Wv_m, Wv_d, W1, W2, out);
}

// round 5
// speedup vs baseline: 1.9282x; 1.3407x over previous
#include <cuda_runtime.h>
#include <cuda_bf16.h>
#include <cstdint>

#define C   128
#define LD  132
#define TILE 64
#define THREADS 512
#define RPW 4
#define EPSF 1e-8f

__device__ float g_Mm[C * C];
__device__ float g_Md[C * C];
// weights pre-split/packed as MMA B-fragments: [k2*128+n] = {W[2k2][n], W[2k2+1][n]}
__device__ uint32_t g_Bh[6][64 * C];
__device__ uint32_t g_Bl[6][64 * C];

__device__ __forceinline__ void split_pack(float x0, float x1, uint32_t& h, uint32_t& l) {
    uint32_t u0 = __float_as_uint(x0), u1 = __float_as_uint(x1);
    h = __byte_perm(u0, u1, 0x7632);  // {top16(x0), top16(x1)}
    float l0 = x0 - __uint_as_float(u0 & 0xFFFF0000u);
    float l1 = x1 - __uint_as_float(u1 & 0xFFFF0000u);
    __nv_bfloat162 t = __floats2bfloat162_rn(l0, l1);
    l = *(uint32_t*)&t;
}

__global__ void precompute_M_kernel(const float* __restrict__ Wq_m, const float* __restrict__ Wk_m,
                                    const float* __restrict__ Wq_d, const float* __restrict__ Wk_d) {
    const float* Wq = blockIdx.y ? Wq_d : Wq_m;
    const float* Wk = blockIdx.y ? Wk_d : Wk_m;
    float* M = blockIdx.y ? g_Md : g_Mm;
    int i = blockIdx.x, t = threadIdx.x;
    __shared__ float qrow[C];
    qrow[t] = Wq[i * C + t];
    __syncthreads();
    const float* wkr = Wk + t * C;
    float acc = 0.f;
#pragma unroll 8
    for (int j = 0; j < C; j++) acc += qrow[j] * wkr[j];
    M[i * C + t] = acc * 0.08838834764831845f;
}

__global__ void bake_kernel(const float* __restrict__ Wg, const float* __restrict__ Wvm,
                            const float* __restrict__ Wvd, const float* __restrict__ W1) {
    int w = blockIdx.y;
    const float* src = (w == 0) ? Wg : (w == 1) ? g_Mm : (w == 2) ? Wvm
                      : (w == 3) ? g_Md : (w == 4) ? Wvd : W1;
    int idx = blockIdx.x * blockDim.x + threadIdx.x;  // 0..8191
    int k2 = idx >> 7, n = idx & 127;
    float v0 = src[(2 * k2) * C + n], v1 = src[(2 * k2 + 1) * C + n];
    uint32_t h, l;
    split_pack(v0, v1, h, l);
    g_Bh[w][idx] = h;
    g_Bl[w][idx] = l;
}

__device__ __forceinline__ void mma16816(float* d, const uint32_t* a, uint32_t b0, uint32_t b1) {
    asm volatile(
        "mma.sync.aligned.m16n8k16.row.col.f32.bf16.bf16.f32 "
        "{%0,%1,%2,%3}, {%4,%5,%6,%7}, {%8,%9}, {%0,%1,%2,%3};"
        : "+f"(d[0]), "+f"(d[1]), "+f"(d[2]), "+f"(d[3])
        : "r"(a[0]), "r"(a[1]), "r"(a[2]), "r"(a[3]), "r"(b0), "r"(b1));
}

// D[64,128] = A[64,128] @ W (W pre-split in sWH/sWL fragment layout, stride LD).
// 16 warps: rows (w&3)*16..+15, cols (w>>2)*32..+31. D may alias sWH region.
__device__ void wgemm(const float* sA, const uint32_t* pH, const uint32_t* pL, float* sD,
                      int tid) {
    const int lane = tid & 31;
    const int rb = ((tid >> 5) & 3) * 16, ch = (tid >> 7) * 32;
    const int g = lane >> 2, t = lane & 3;
    float acc[4][4];
#pragma unroll
    for (int nt = 0; nt < 4; nt++) acc[nt][0] = acc[nt][1] = acc[nt][2] = acc[nt][3] = 0.f;

#pragma unroll 1
    for (int k0 = 0; k0 < C; k0 += 16) {
        const float* Ar = sA + (rb + g) * LD + k0 + 2 * t;
        float2 p0 = *(const float2*)(Ar);
        float2 p1 = *(const float2*)(Ar + 8 * LD);
        float2 p2 = *(const float2*)(Ar + 8);
        float2 p3 = *(const float2*)(Ar + 8 * LD + 8);
        uint32_t ah[4], al[4];
        split_pack(p0.x, p0.y, ah[0], al[0]);
        split_pack(p1.x, p1.y, ah[1], al[1]);
        split_pack(p2.x, p2.y, ah[2], al[2]);
        split_pack(p3.x, p3.y, ah[3], al[3]);
        const uint32_t* BH = pH + ((k0 >> 1) + t) * LD + ch + g;
        const uint32_t* BL = pL + ((k0 >> 1) + t) * LD + ch + g;
#pragma unroll
        for (int nt = 0; nt < 4; nt++) {
            uint32_t bh0 = BH[nt * 8], bh1 = BH[4 * LD + nt * 8];
            uint32_t bl0 = BL[nt * 8], bl1 = BL[4 * LD + nt * 8];
            mma16816(acc[nt], ah, bh0, bh1);
            mma16816(acc[nt], al, bh0, bh1);
            mma16816(acc[nt], ah, bl0, bl1);
        }
    }
    __syncthreads();
#pragma unroll
    for (int nt = 0; nt < 4; nt++) {
        float* Dp = sD + (rb + g) * LD + ch + nt * 8 + 2 * t;
        Dp[0] = acc[nt][0];
        Dp[1] = acc[nt][1];
        Dp[8 * LD] = acc[nt][2];
        Dp[8 * LD + 1] = acc[nt][3];
    }
    __syncthreads();
}

__global__ void __launch_bounds__(THREADS, 1)
fused_kernel(const float* __restrict__ em, const float* __restrict__ ed,
             const float* __restrict__ W2, float* __restrict__ out) {
    extern __shared__ float sm[];
    float* sEM = sm;
    float* sED = sEM + TILE * LD;
    float* sX0 = sED + TILE * LD;
    float* sX1 = sX0 + TILE * LD;
    uint32_t* sWH = (uint32_t*)(sX1 + TILE * LD);  // 64*LD u32
    uint32_t* sWL = sWH + 64 * LD;                 // 64*LD u32
    float* sW2 = (float*)(sWL + 64 * LD);
    float* sT = (float*)sWH;  // fp32 scratch for T / H (aliases hi array)

    const int tid = threadIdx.x;
    const int lane = tid & 31;
    const int r0 = (tid >> 5) * RPW;
    const long base = (long)blockIdx.x * TILE;

    {
        const float4* ge = (const float4*)(em + base * C);
        const float4* gd = (const float4*)(ed + base * C);
        for (int i = tid; i < TILE * 32; i += THREADS) {
            int r = i >> 5, c4 = i & 31;
            ((float4*)(sEM + r * LD))[c4] = ge[i];
            ((float4*)(sED + r * LD))[c4] = gd[i];
        }
        if (tid < C) sW2[tid] = W2[tid];
    }
    __syncthreads();

    // adjacency scalars
    float aS[RPW], bS[RPW];
#pragma unroll
    for (int rr = 0; rr < RPW; rr++) {
        const float* pe = sEM + (r0 + rr) * LD;
        const float* pd = sED + (r0 + rr) * LD;
        float sa = 0.f, q0 = 0.f, q1 = 0.f, dp = 0.f;
#pragma unroll
        for (int q = 0; q < 4; q++) {
            int k = lane + 32 * q;
            float e = pe[k], d = pd[k];
            sa += fabsf(e - d); q0 += e * e; q1 += d * d; dp += e * d;
        }
#pragma unroll
        for (int o = 16; o; o >>= 1) {
            sa += __shfl_xor_sync(~0u, sa, o);
            q0 += __shfl_xor_sync(~0u, q0, o);
            q1 += __shfl_xor_sync(~0u, q1, o);
            dp += __shfl_xor_sync(~0u, dp, o);
        }
        float m = sa;
        float cosv = dp / (sqrtf(q0 + EPSF) * sqrtf(q1 + EPSF));
        float cp = cosv > 0.f ? cosv : 0.01f * cosv;
        aS[rr] = fminf(1.f / (1.f + cp), 1.f / (1.f + m));
        bS[rr] = fminf(cp / (1.f + cp), m / (1.f + m));
    }

    auto load_w = [&](int w) {
        __syncthreads();
        const uint4* gh = (const uint4*)g_Bh[w];
        const uint4* gl = (const uint4*)g_Bl[w];
        for (int i = tid; i < 64 * 32; i += THREADS) {
            int r = i >> 5, c4 = i & 31;
            ((uint4*)(sWH + r * LD))[c4] = gh[i];
            ((uint4*)(sWL + r * LD))[c4] = gl[i];
        }
        __syncthreads();
    };

    // ---- GCN ----
    load_w(0);
    wgemm(sEM, sWH, sWL, sX0, tid);
    wgemm(sED, sWH, sWL, sX1, tid);
#pragma unroll
    for (int rr = 0; rr < RPW; rr++) {
        int r = r0 + rr;
        float a = aS[rr], b = bS[rr];
#pragma unroll
        for (int q = 0; q < 4; q++) {
            int k = lane + 32 * q;
            float g0 = sX0[r * LD + k], g1 = sX1[r * LD + k];
            sX0[r * LD + k] = fmaxf(a * g0 + b * g1, 0.f) + sEM[r * LD + k];
            sX1[r * LD + k] = fmaxf(b * g0 + a * g1, 0.f) + sED[r * LD + k];
        }
    }

    auto attn_epi = [&](const float* sF, float* sX) {
#pragma unroll
        for (int rr = 0; rr < RPW; rr++) {
            int r = r0 + rr;
            float s0 = 0.f, s1 = 0.f;
#pragma unroll
            for (int q = 0; q < 4; q++) {
                int k = lane + 32 * q;
                float tv = sT[r * LD + k];
                s0 += tv * sF[r * LD + k];
                s1 += tv * sX[r * LD + k];
            }
#pragma unroll
            for (int o = 16; o; o >>= 1) {
                s0 += __shfl_xor_sync(~0u, s0, o);
                s1 += __shfl_xor_sync(~0u, s1, o);
            }
            float mx = fmaxf(s0, s1);
            float e0 = expf(s0 - mx), e1 = expf(s1 - mx);
            float inv = 1.f / (e0 + e1);
            float w0 = e0 * inv, w1 = e1 * inv;
#pragma unroll
            for (int q = 0; q < 4; q++) {
                int k = lane + 32 * q;
                sX[r * LD + k] = w0 * sF[r * LD + k] + w1 * sX[r * LD + k];
            }
        }
        __syncthreads();
    };

    // ---- m branch ----
    load_w(1);
    wgemm(sX0, sWH, sWL, sT, tid);
    attn_epi(sEM, sX0);
    load_w(2);
    wgemm(sX0, sWH, sWL, sEM, tid);  // mLA -> sEM

    // ---- d branch ----
    load_w(3);
    wgemm(sX1, sWH, sWL, sT, tid);
    attn_epi(sED, sX1);
    load_w(4);
    wgemm(sX1, sWH, sWL, sED, tid);  // dLA -> sED

    // ---- head ----
#pragma unroll
    for (int rr = 0; rr < RPW; rr++) {
        int r = r0 + rr;
#pragma unroll
        for (int q = 0; q < 4; q++) {
            int k = lane + 32 * q;
            sX0[r * LD + k] = sEM[r * LD + k] * sED[r * LD + k];
        }
    }
    load_w(5);
    wgemm(sX0, sWH, sWL, sT, tid);
#pragma unroll
    for (int rr = 0; rr < RPW; rr++) {
        int r = r0 + rr;
        float p = 0.f;
#pragma unroll
        for (int q = 0; q < 4; q++) {
            int k = lane + 32 * q;
            p += fmaxf(sT[r * LD + k], 0.f) * sW2[k];
        }
#pragma unroll
        for (int o = 16; o; o >>= 1) p += __shfl_xor_sync(~0u, p, o);
        if (lane == 0) out[base + r] = 1.f / (1.f + expf(-p));
    }
}

extern "C" void kernel_launch(void* const* d_in, const int* in_sizes, int n_in,
                              void* d_out, int out_size) {
    const float* em    = (const float*)d_in[0];
    const float* ed    = (const float*)d_in[1];
    const float* W_gcn = (const float*)d_in[2];
    const float* Wq_m  = (const float*)d_in[3];
    const float* Wk_m  = (const float*)d_in[4];
    const float* Wv_m  = (const float*)d_in[5];
    const float* Wq_d  = (const float*)d_in[6];
    const float* Wk_d  = (const float*)d_in[7];
    const float* Wv_d  = (const float*)d_in[8];
    const float* W1    = (const float*)d_in[9];
    const float* W2    = (const float*)d_in[10];
    float* out = (float*)d_out;

    const int B = in_sizes[0] / C;
    const int smem_bytes = (6 * TILE * LD + C) * (int)sizeof(float);  // ~203 KB

    precompute_M_kernel<<<dim3(C, 2), C>>>(Wq_m, Wk_m, Wq_d, Wk_d);
    bake_kernel<<<dim3(8192 / 256, 6), 256>>>(W_gcn, Wv_m, Wv_d, W1);

    cudaFuncSetAttribute(fused_kernel,
                         cudaFuncAttributeMaxDynamicSharedMemorySize, smem_bytes);
    fused_kernel<<<B / TILE, THREADS, smem_bytes>>>(em, ed, W2, out);
}